// round 7
// baseline (speedup 1.0000x reference)
#include <cuda_runtime.h>
#include <cstdint>

#define E_CNT 100000
#define NDST  10000
#define OUTC  2048

// ---------------- small device scratch (CSR only) ----------------
__device__ int g_counts[NDST];
__device__ int g_cursor[NDST];
__device__ int g_eid   [E_CNT];

// ---------------- prologue kernels ----------------
__global__ void zero_cnt_k() {
    int i = blockIdx.x * blockDim.x + threadIdx.x;
    if (i < NDST) g_counts[i] = 0;
}
__global__ void hist_k(const int* __restrict__ dst) {
    int e = blockIdx.x * blockDim.x + threadIdx.x;
    if (e < E_CNT) atomicAdd(&g_counts[dst[e]], 1);
}
__global__ void scan_k() {
    __shared__ int ss[1024];
    const int tid = threadIdx.x;
    const int CH = 10;
    int base = tid * CH, loc[CH], s = 0;
#pragma unroll
    for (int i = 0; i < CH; i++) {
        int idx = base + i;
        int v = (idx < NDST) ? g_counts[idx] : 0;
        loc[i] = s; s += v;
    }
    ss[tid] = s; __syncthreads();
    for (int off = 1; off < 1024; off <<= 1) {
        int v = 0;
        if (tid >= off) v = ss[tid - off];
        __syncthreads();
        if (tid >= off) ss[tid] += v;
        __syncthreads();
    }
    int excl = (tid == 0) ? 0 : ss[tid - 1];
#pragma unroll
    for (int i = 0; i < CH; i++) {
        int idx = base + i;
        if (idx < NDST) g_cursor[idx] = excl + loc[i];
    }
}
__global__ void fill_k(const int* __restrict__ dst) {
    int e = blockIdx.x * blockDim.x + threadIdx.x;
    if (e < E_CNT) {
        int p = atomicAdd(&g_cursor[dst[e]], 1);
        g_eid[p] = e;
    }
}
__global__ void zero_out_k(float4* __restrict__ out, int n4) {
    int i = blockIdx.x * blockDim.x + threadIdx.x;
    if (i < n4) out[i] = make_float4(0.f, 0.f, 0.f, 0.f);
}

// ---------------- tf32 mma helpers ----------------
__device__ __forceinline__ uint32_t tf32c(float x) {
    uint32_t r; asm("cvt.rna.tf32.f32 %0, %1;" : "=r"(r) : "f"(x)); return r;
}
__device__ __forceinline__ void mma8(float* c, uint32_t a0, uint32_t a1,
                                     uint32_t a2, uint32_t a3,
                                     uint32_t b0, uint32_t b1) {
    asm("mma.sync.aligned.m16n8k8.row.col.f32.tf32.tf32.f32 "
        "{%0,%1,%2,%3}, {%4,%5,%6,%7}, {%8,%9}, {%0,%1,%2,%3};"
        : "+f"(c[0]), "+f"(c[1]), "+f"(c[2]), "+f"(c[3])
        : "r"(a0), "r"(a1), "r"(a2), "r"(a3), "r"(b0), "r"(b1));
}

// ---------------- smem layout (float offsets) ----------------
// Hs [64][132] | WT [128][68] (W1T / W2T-half) | TPW [64][128] (As[64][68] aliases)
// SHs [64][16] | 192 ints
#define F_HS   0
#define F_WT   8448
#define F_TPW  17152
#define F_SHS  25344
#define F_END  26368
#define SMEM_BYTES ((F_END + 192) * 4)

// ---------------- fused kernel: tf32 MMA MLP + TP + segment scatter --------
__global__ __launch_bounds__(256, 2) void fused_k(
    const float* __restrict__ src_features,
    const float* __restrict__ edge_sh,
    const float* __restrict__ edge_emb,
    const float* __restrict__ W1,
    const float* __restrict__ W2,
    const int*   __restrict__ src,
    const int*   __restrict__ dst,
    float*       __restrict__ out)
{
    extern __shared__ float sm[];
    float* Hs  = sm + F_HS;     // [64][132] tf32 values
    float* WT  = sm + F_WT;     // [128][68] B^T tiles (tf32)
    float* TPW = sm + F_TPW;    // [64][128]; As [64][68] aliases
    float* SHs = sm + F_SHS;    // [64][16]
    float* As  = TPW;
    int*   Es  = (int*)(sm + F_END);
    int*   Ss  = Es + 64;
    int*   Ds  = Ss + 64;

    const int tid = threadIdx.x;
    const int w   = tid >> 5;
    const int t   = tid & 31;
    const int gp  = t >> 2;       // groupID 0..7
    const int tg  = t & 3;        // thread-in-group 0..3
    const int r0  = (w & 3) * 16; // warp row-tile base (edges)
    const int n0  = (w >> 2) * 64;// warp col base (8 n-tiles of 8)

    // ---- stage edge metadata (pads replicate last edge; SH pads -> 0) ----
    const int pos0 = blockIdx.x * 64;
    const int nE   = (E_CNT - pos0 < 64) ? (E_CNT - pos0) : 64;
    if (tid < 64) {
        int sl = (tid < nE) ? tid : (nE - 1);
        int e  = g_eid[pos0 + sl];
        Es[tid] = e; Ss[tid] = src[e]; Ds[tid] = dst[e];
    }
    __syncthreads();

    // ---- stage As=EMB [64][68] (tf32), W1T [128][68] (tf32,*1/8), SHs ----
#pragma unroll
    for (int it = 0; it < 4; it++) {           // EMB: 64 x 16 float4
        int li = tid + it * 256;
        int slot = li >> 4, f = li & 15;
        float4 v = *(const float4*)&edge_emb[(size_t)Es[slot] * 64 + f * 4];
        float* p = &As[slot * 68 + f * 4];
        p[0] = __uint_as_float(tf32c(v.x)); p[1] = __uint_as_float(tf32c(v.y));
        p[2] = __uint_as_float(tf32c(v.z)); p[3] = __uint_as_float(tf32c(v.w));
    }
#pragma unroll
    for (int it = 0; it < 8; it++) {           // W1T[n][k] = W1[k][n]/8
        int li = tid + it * 256;
        int k = li >> 5, n4 = (li & 31) * 4;
        float4 v = *(const float4*)&W1[(size_t)k * 128 + n4];
        WT[(n4 + 0) * 68 + k] = __uint_as_float(tf32c(v.x * 0.125f));
        WT[(n4 + 1) * 68 + k] = __uint_as_float(tf32c(v.y * 0.125f));
        WT[(n4 + 2) * 68 + k] = __uint_as_float(tf32c(v.z * 0.125f));
        WT[(n4 + 3) * 68 + k] = __uint_as_float(tf32c(v.w * 0.125f));
    }
    {                                          // SHs: 64 x 4 float4 (zero pads)
        int slot = tid >> 2, j = tid & 3;
        float4 v = make_float4(0.f, 0.f, 0.f, 0.f);
        if (slot < nE)
            v = *(const float4*)&edge_sh[(size_t)Es[slot] * 16 + j * 4];
        *(float4*)&SHs[slot * 16 + j * 4] = v;
    }
    __syncthreads();

    // ---- GEMM1: Hs = silu(EMB @ W1^T), M64 N128 K64, tf32 mma ----
    {
        float acc[8][4];
#pragma unroll
        for (int j = 0; j < 8; j++)
#pragma unroll
            for (int q = 0; q < 4; q++) acc[j][q] = 0.f;

#pragma unroll
        for (int k0 = 0; k0 < 64; k0 += 8) {
            uint32_t a0 = __float_as_uint(As[(r0 + gp)     * 68 + k0 + tg]);
            uint32_t a1 = __float_as_uint(As[(r0 + gp + 8) * 68 + k0 + tg]);
            uint32_t a2 = __float_as_uint(As[(r0 + gp)     * 68 + k0 + tg + 4]);
            uint32_t a3 = __float_as_uint(As[(r0 + gp + 8) * 68 + k0 + tg + 4]);
#pragma unroll
            for (int j = 0; j < 8; j++) {
                uint32_t b0 = __float_as_uint(WT[(n0 + j * 8 + gp) * 68 + k0 + tg]);
                uint32_t b1 = __float_as_uint(WT[(n0 + j * 8 + gp) * 68 + k0 + tg + 4]);
                mma8(acc[j], a0, a1, a2, a3, b0, b1);
            }
        }
        // epilogue: silu -> tf32 -> Hs[64][132]
#pragma unroll
        for (int j = 0; j < 8; j++) {
            int c = n0 + j * 8 + 2 * tg;
            int rA = r0 + gp, rB = r0 + gp + 8;
            float x0 = acc[j][0], x1 = acc[j][1], x2 = acc[j][2], x3 = acc[j][3];
            x0 = x0 / (1.f + __expf(-x0)); x1 = x1 / (1.f + __expf(-x1));
            x2 = x2 / (1.f + __expf(-x2)); x3 = x3 / (1.f + __expf(-x3));
            Hs[rA * 132 + c]     = __uint_as_float(tf32c(x0));
            Hs[rA * 132 + c + 1] = __uint_as_float(tf32c(x1));
            Hs[rB * 132 + c]     = __uint_as_float(tf32c(x2));
            Hs[rB * 132 + c + 1] = __uint_as_float(tf32c(x3));
        }
    }
    __syncthreads();   // Hs ready; WT and As(TPW) free

    // ---- per-l: GEMM2 (tf32 mma) + fold x + run-length segment scatter ----
    const float w2s = 0.08838834764831845f;    // 1/sqrt(128)

    for (int l = 0; l < 4; l++) {
        float acc[8][4];
#pragma unroll
        for (int j = 0; j < 8; j++)
#pragma unroll
            for (int q = 0; q < 4; q++) acc[j][q] = 0.f;

#pragma unroll
        for (int kh = 0; kh < 2; kh++) {
            // stage W2T[n][k] = W2[kh*64+k][l*128+n] * w2s  (tf32)
#pragma unroll
            for (int it = 0; it < 8; it++) {
                int li = tid + it * 256;
                int k = li >> 5, n4 = (li & 31) * 4;
                float4 v = *(const float4*)&W2[(size_t)(kh * 64 + k) * 512 + l * 128 + n4];
                WT[(n4 + 0) * 68 + k] = __uint_as_float(tf32c(v.x * w2s));
                WT[(n4 + 1) * 68 + k] = __uint_as_float(tf32c(v.y * w2s));
                WT[(n4 + 2) * 68 + k] = __uint_as_float(tf32c(v.z * w2s));
                WT[(n4 + 3) * 68 + k] = __uint_as_float(tf32c(v.w * w2s));
            }
            __syncthreads();

#pragma unroll
            for (int k0 = 0; k0 < 64; k0 += 8) {
                int kk = kh * 64 + k0;
                uint32_t a0 = __float_as_uint(Hs[(r0 + gp)     * 132 + kk + tg]);
                uint32_t a1 = __float_as_uint(Hs[(r0 + gp + 8) * 132 + kk + tg]);
                uint32_t a2 = __float_as_uint(Hs[(r0 + gp)     * 132 + kk + tg + 4]);
                uint32_t a3 = __float_as_uint(Hs[(r0 + gp + 8) * 132 + kk + tg + 4]);
#pragma unroll
                for (int j = 0; j < 8; j++) {
                    uint32_t b0 = __float_as_uint(WT[(n0 + j * 8 + gp) * 68 + k0 + tg]);
                    uint32_t b1 = __float_as_uint(WT[(n0 + j * 8 + gp) * 68 + k0 + tg + 4]);
                    mma8(acc[j], a0, a1, a2, a3, b0, b1);
                }
            }
            __syncthreads();   // WT reads complete before restage / TPW write
        }

        // fold: TPW[r][c] = acc * x_src[src[r]][c]   (float2, L2-resident x)
#pragma unroll
        for (int j = 0; j < 8; j++) {
            int c = n0 + j * 8 + 2 * tg;
            int rA = r0 + gp, rB = r0 + gp + 8;
            float2 xA = *(const float2*)&src_features[(size_t)Ss[rA] * 128 + c];
            float2 xB = *(const float2*)&src_features[(size_t)Ss[rB] * 128 + c];
            *(float2*)&TPW[rA * 128 + c] = make_float2(acc[j][0] * xA.x, acc[j][1] * xA.y);
            *(float2*)&TPW[rB * 128 + c] = make_float2(acc[j][2] * xB.x, acc[j][3] * xB.y);
        }
        __syncthreads();

        // scatter: run-length reduce over 64 dst-sorted edges
        {
            const int d    = 2 * l + 1;
            const int soff = l * l;
            const int ob   = (l == 0) ? 0 : (l == 1) ? 128 : (l == 2) ? 512 : 1152;
            const int ncol = 128 * d;
            for (int q = tid; q < ncol; q += 256) {
                const int c = q / d;
                const int s = q - c * d;
                float a = 0.f;
                int cur = Ds[0];
#pragma unroll 8
                for (int e = 0; e < 64; e++) {
                    int dn = Ds[e];
                    if (dn != cur) {
                        atomicAdd(&out[(size_t)cur * OUTC + ob + q], a);
                        a = 0.f; cur = dn;
                    }
                    a += TPW[e * 128 + c] * SHs[e * 16 + soff + s];
                }
                atomicAdd(&out[(size_t)cur * OUTC + ob + q], a);
            }
        }
        __syncthreads();
    }
}

// ---------------- launch ----------------
extern "C" void kernel_launch(void* const* d_in, const int* in_sizes, int n_in,
                              void* d_out, int out_size)
{
    const float* src_features = (const float*)d_in[0];
    const float* edge_sh      = (const float*)d_in[1];
    const float* edge_emb     = (const float*)d_in[2];
    const float* W1           = (const float*)d_in[3];
    const float* W2           = (const float*)d_in[4];
    const int*   src          = (const int*)d_in[5];
    const int*   dst          = (const int*)d_in[6];
    float*       out          = (float*)d_out;
    (void)in_sizes; (void)n_in; (void)out_size;

    static bool attr_done = false;
    if (!attr_done) {
        cudaFuncSetAttribute(fused_k, cudaFuncAttributeMaxDynamicSharedMemorySize,
                             SMEM_BYTES);
        attr_done = true;
    }

    // CSR build
    zero_cnt_k<<<(NDST + 255) / 256, 256>>>();
    hist_k<<<(E_CNT + 255) / 256, 256>>>(dst);
    scan_k<<<1, 1024>>>();
    fill_k<<<(E_CNT + 255) / 256, 256>>>(dst);

    // zero output (atomic accumulation target)
    const int n4 = NDST * OUTC / 4;
    zero_out_k<<<(n4 + 255) / 256, 256>>>((float4*)out, n4);

    // fused tf32-MMA MLP + TP + scatter (64 edges/block, 2 CTAs/SM)
    const int nblk = (E_CNT + 63) / 64;
    fused_k<<<nblk, 256, SMEM_BYTES>>>(src_features, edge_sh, edge_emb,
                                       W1, W2, src, dst, out);
}

// round 9
// speedup vs baseline: 1.0694x; 1.0694x over previous
#include <cuda_runtime.h>
#include <cuda_fp16.h>
#include <cstdint>

#define E_CNT 100000
#define NDST  10000
#define OUTC  2048

// ---------------- small device scratch (CSR only) ----------------
__device__ int g_counts[NDST];
__device__ int g_cursor[NDST];
__device__ int g_eid   [E_CNT];

// ---------------- prologue kernels ----------------
__global__ void zero_cnt_k() {
    int i = blockIdx.x * blockDim.x + threadIdx.x;
    if (i < NDST) g_counts[i] = 0;
}
__global__ void hist_k(const int* __restrict__ dst) {
    int e = blockIdx.x * blockDim.x + threadIdx.x;
    if (e < E_CNT) atomicAdd(&g_counts[dst[e]], 1);
}
__global__ void scan_k() {
    __shared__ int ss[1024];
    const int tid = threadIdx.x;
    const int CH = 10;
    int base = tid * CH, loc[CH], s = 0;
#pragma unroll
    for (int i = 0; i < CH; i++) {
        int idx = base + i;
        int v = (idx < NDST) ? g_counts[idx] : 0;
        loc[i] = s; s += v;
    }
    ss[tid] = s; __syncthreads();
    for (int off = 1; off < 1024; off <<= 1) {
        int v = 0;
        if (tid >= off) v = ss[tid - off];
        __syncthreads();
        if (tid >= off) ss[tid] += v;
        __syncthreads();
    }
    int excl = (tid == 0) ? 0 : ss[tid - 1];
#pragma unroll
    for (int i = 0; i < CH; i++) {
        int idx = base + i;
        if (idx < NDST) g_cursor[idx] = excl + loc[i];
    }
}
__global__ void fill_k(const int* __restrict__ dst) {
    int e = blockIdx.x * blockDim.x + threadIdx.x;
    if (e < E_CNT) {
        int p = atomicAdd(&g_cursor[dst[e]], 1);
        g_eid[p] = e;
    }
}
__global__ void zero_out_k(float4* __restrict__ out, int n4) {
    int i = blockIdx.x * blockDim.x + threadIdx.x;
    if (i < n4) out[i] = make_float4(0.f, 0.f, 0.f, 0.f);
}

// ---------------- fp16 mma helper ----------------
__device__ __forceinline__ void mma16(float* c, uint32_t a0, uint32_t a1,
                                      uint32_t a2, uint32_t a3,
                                      uint32_t b0, uint32_t b1) {
    asm("mma.sync.aligned.m16n8k16.row.col.f32.f16.f16.f32 "
        "{%0,%1,%2,%3}, {%4,%5,%6,%7}, {%8,%9}, {%0,%1,%2,%3};"
        : "+f"(c[0]), "+f"(c[1]), "+f"(c[2]), "+f"(c[3])
        : "r"(a0), "r"(a1), "r"(a2), "r"(a3), "r"(b0), "r"(b1));
}

// ---------------- smem layout ----------------
// halves: Hs [64][136] 17408B | WT [128][72] 18432B
// floats: TPW [64][128] 32768B (As half[64][72]=9216B aliases) | SHs [64][16] 4096B
#define B_HS    0
#define B_WT    17408
#define B_TPW   35840
#define B_SHS   68608
#define B_INTS  72704
#define SMEM_BYTES (B_INTS + 192 * 4)

// ---------------- fused kernel: fp16 MMA MLP + TP + segment scatter --------
__global__ __launch_bounds__(256, 2) void fused_k(
    const float* __restrict__ src_features,
    const float* __restrict__ edge_sh,
    const float* __restrict__ edge_emb,
    const float* __restrict__ W1,
    const float* __restrict__ W2,
    const int*   __restrict__ src,
    const int*   __restrict__ dst,
    float*       __restrict__ out)
{
    extern __shared__ char smc[];
    __half* Hs  = (__half*)(smc + B_HS);    // [64][136]
    __half* WT  = (__half*)(smc + B_WT);    // [128][72]  B^T (k-range 0..63 per stage)
    float*  TPW = (float*) (smc + B_TPW);   // [64][128]
    __half* As  = (__half*)(smc + B_TPW);   // [64][72]   aliases TPW
    float*  SHs = (float*) (smc + B_SHS);   // [64][16]
    int*    Es  = (int*)   (smc + B_INTS);
    int*    Ss  = Es + 64;
    int*    Ds  = Ss + 64;

    const int tid = threadIdx.x;
    const int w   = tid >> 5;
    const int t   = tid & 31;
    const int gp  = t >> 2;        // groupID 0..7
    const int tg  = t & 3;         // thread-in-group 0..3
    const int r0  = (w & 3) * 16;  // warp row base (edges)
    const int n0  = (w >> 2) * 64; // warp col base

    // ---- stage edge metadata (pads replicate last edge; SH pads -> 0) ----
    const int pos0 = blockIdx.x * 64;
    const int nE   = (E_CNT - pos0 < 64) ? (E_CNT - pos0) : 64;
    if (tid < 64) {
        int sl = (tid < nE) ? tid : (nE - 1);
        int e  = g_eid[pos0 + sl];
        Es[tid] = e; Ss[tid] = src[e]; Ds[tid] = dst[e];
    }
    __syncthreads();

    // ---- stage As=EMB (half), W1T (half, *1/8), SHs ----
#pragma unroll
    for (int it = 0; it < 4; it++) {           // EMB: 64 x 16 float4 -> half2 pairs
        int li = tid + it * 256;
        int slot = li >> 4, f = li & 15;
        float4 v = *(const float4*)&edge_emb[(size_t)Es[slot] * 64 + f * 4];
        __half2* p = (__half2*)&As[slot * 72 + f * 4];
        p[0] = __floats2half2_rn(v.x, v.y);
        p[1] = __floats2half2_rn(v.z, v.w);
    }
#pragma unroll
    for (int it = 0; it < 8; it++) {           // W1T[n][k] = W1[k][n]/8  (k=0..63)
        int li = tid + it * 256;
        int k = li >> 5, n4 = (li & 31) * 4;
        float4 v = *(const float4*)&W1[(size_t)k * 128 + n4];
        WT[(n4 + 0) * 72 + k] = __float2half_rn(v.x * 0.125f);
        WT[(n4 + 1) * 72 + k] = __float2half_rn(v.y * 0.125f);
        WT[(n4 + 2) * 72 + k] = __float2half_rn(v.z * 0.125f);
        WT[(n4 + 3) * 72 + k] = __float2half_rn(v.w * 0.125f);
    }
    {                                          // SHs: 64 x 4 float4 (zero pads)
        int slot = tid >> 2, j = tid & 3;
        float4 v = make_float4(0.f, 0.f, 0.f, 0.f);
        if (slot < nE)
            v = *(const float4*)&edge_sh[(size_t)Es[slot] * 16 + j * 4];
        *(float4*)&SHs[slot * 16 + j * 4] = v;
    }
    __syncthreads();

    // ---- GEMM1: Hs = silu(EMB @ W1^T), M64 N128 K64, fp16 mma ----
    {
        float acc[8][4];
#pragma unroll
        for (int j = 0; j < 8; j++)
#pragma unroll
            for (int q = 0; q < 4; q++) acc[j][q] = 0.f;

#pragma unroll
        for (int k0 = 0; k0 < 64; k0 += 16) {
            uint32_t a0 = *(uint32_t*)&As[(r0 + gp)     * 72 + k0 + 2 * tg];
            uint32_t a1 = *(uint32_t*)&As[(r0 + gp + 8) * 72 + k0 + 2 * tg];
            uint32_t a2 = *(uint32_t*)&As[(r0 + gp)     * 72 + k0 + 2 * tg + 8];
            uint32_t a3 = *(uint32_t*)&As[(r0 + gp + 8) * 72 + k0 + 2 * tg + 8];
#pragma unroll
            for (int j = 0; j < 8; j++) {
                const __half* bp = &WT[(n0 + j * 8 + gp) * 72 + k0 + 2 * tg];
                uint32_t b0 = *(uint32_t*)bp;
                uint32_t b1 = *(uint32_t*)(bp + 8);
                mma16(acc[j], a0, a1, a2, a3, b0, b1);
            }
        }
        // epilogue: silu -> half -> Hs
#pragma unroll
        for (int j = 0; j < 8; j++) {
            int c = n0 + j * 8 + 2 * tg;
            int rA = r0 + gp, rB = r0 + gp + 8;
            float x0 = acc[j][0], x1 = acc[j][1], x2 = acc[j][2], x3 = acc[j][3];
            x0 = x0 / (1.f + __expf(-x0)); x1 = x1 / (1.f + __expf(-x1));
            x2 = x2 / (1.f + __expf(-x2)); x3 = x3 / (1.f + __expf(-x3));
            *(__half2*)&Hs[rA * 136 + c] = __floats2half2_rn(x0, x1);
            *(__half2*)&Hs[rB * 136 + c] = __floats2half2_rn(x2, x3);
        }
    }
    __syncthreads();   // Hs ready; WT and As(TPW) free

    // ---- per-l: GEMM2 (fp16 mma) + fold x + run-length segment scatter ----
    const float w2s = 0.08838834764831845f;    // 1/sqrt(128)

    for (int l = 0; l < 4; l++) {
        float acc[8][4];
#pragma unroll
        for (int j = 0; j < 8; j++)
#pragma unroll
            for (int q = 0; q < 4; q++) acc[j][q] = 0.f;

        // K split into two 64-halves; WT[n][0..63] re-staged per half.
#pragma unroll
        for (int kh = 0; kh < 2; kh++) {
            __syncthreads();   // prior WT reads (or prior-l TPW use) complete
#pragma unroll
            for (int it = 0; it < 8; it++) {   // stage WT[n][k] = W2[kh*64+k][l*128+n]*w2s
                int li = tid + it * 256;
                int k = li >> 5, n4 = (li & 31) * 4;
                float4 v = *(const float4*)&W2[(size_t)(kh * 64 + k) * 512 + l * 128 + n4];
                WT[(n4 + 0) * 72 + k] = __float2half_rn(v.x * w2s);
                WT[(n4 + 1) * 72 + k] = __float2half_rn(v.y * w2s);
                WT[(n4 + 2) * 72 + k] = __float2half_rn(v.z * w2s);
                WT[(n4 + 3) * 72 + k] = __float2half_rn(v.w * w2s);
            }
            __syncthreads();

#pragma unroll
            for (int k0 = 0; k0 < 64; k0 += 16) {
                int kk = kh * 64 + k0;
                uint32_t a0 = *(uint32_t*)&Hs[(r0 + gp)     * 136 + kk + 2 * tg];
                uint32_t a1 = *(uint32_t*)&Hs[(r0 + gp + 8) * 136 + kk + 2 * tg];
                uint32_t a2 = *(uint32_t*)&Hs[(r0 + gp)     * 136 + kk + 2 * tg + 8];
                uint32_t a3 = *(uint32_t*)&Hs[(r0 + gp + 8) * 136 + kk + 2 * tg + 8];
#pragma unroll
                for (int j = 0; j < 8; j++) {
                    const __half* bp = &WT[(n0 + j * 8 + gp) * 72 + k0 + 2 * tg];
                    uint32_t b0 = *(uint32_t*)bp;
                    uint32_t b1 = *(uint32_t*)(bp + 8);
                    mma16(acc[j], a0, a1, a2, a3, b0, b1);
                }
            }
        }
        __syncthreads();   // WT reads done; TPW(As) safe to write

        // fold: TPW[r][c] = acc * x_src[src[r]][c]
#pragma unroll
        for (int j = 0; j < 8; j++) {
            int c = n0 + j * 8 + 2 * tg;
            int rA = r0 + gp, rB = r0 + gp + 8;
            float2 xA = *(const float2*)&src_features[(size_t)Ss[rA] * 128 + c];
            float2 xB = *(const float2*)&src_features[(size_t)Ss[rB] * 128 + c];
            *(float2*)&TPW[rA * 128 + c] = make_float2(acc[j][0] * xA.x, acc[j][1] * xA.y);
            *(float2*)&TPW[rB * 128 + c] = make_float2(acc[j][2] * xB.x, acc[j][3] * xB.y);
        }
        __syncthreads();

        // scatter: run-length reduce over 64 dst-sorted edges
        {
            const int d    = 2 * l + 1;
            const int soff = l * l;
            const int ob   = (l == 0) ? 0 : (l == 1) ? 128 : (l == 2) ? 512 : 1152;
            const int ncol = 128 * d;
            for (int q = tid; q < ncol; q += 256) {
                const int c = q / d;
                const int s = q - c * d;
                float a = 0.f;
                int cur = Ds[0];
#pragma unroll 8
                for (int e = 0; e < 64; e++) {
                    int dn = Ds[e];
                    if (dn != cur) {
                        atomicAdd(&out[(size_t)cur * OUTC + ob + q], a);
                        a = 0.f; cur = dn;
                    }
                    a += TPW[e * 128 + c] * SHs[e * 16 + soff + s];
                }
                atomicAdd(&out[(size_t)cur * OUTC + ob + q], a);
            }
        }
        __syncthreads();
    }
}

// ---------------- launch ----------------
extern "C" void kernel_launch(void* const* d_in, const int* in_sizes, int n_in,
                              void* d_out, int out_size)
{
    const float* src_features = (const float*)d_in[0];
    const float* edge_sh      = (const float*)d_in[1];
    const float* edge_emb     = (const float*)d_in[2];
    const float* W1           = (const float*)d_in[3];
    const float* W2           = (const float*)d_in[4];
    const int*   src          = (const int*)d_in[5];
    const int*   dst          = (const int*)d_in[6];
    float*       out          = (float*)d_out;
    (void)in_sizes; (void)n_in; (void)out_size;

    static bool attr_done = false;
    if (!attr_done) {
        cudaFuncSetAttribute(fused_k, cudaFuncAttributeMaxDynamicSharedMemorySize,
                             SMEM_BYTES);
        attr_done = true;
    }

    // CSR build
    zero_cnt_k<<<(NDST + 255) / 256, 256>>>();
    hist_k<<<(E_CNT + 255) / 256, 256>>>(dst);
    scan_k<<<1, 1024>>>();
    fill_k<<<(E_CNT + 255) / 256, 256>>>(dst);

    // zero output (atomic accumulation target)
    const int n4 = NDST * OUTC / 4;
    zero_out_k<<<(n4 + 255) / 256, 256>>>((float4*)out, n4);

    // fused fp16-MMA MLP + TP + scatter (64 edges/block, 2 CTAs/SM)
    const int nblk = (E_CNT + 63) / 64;
    fused_k<<<nblk, 256, SMEM_BYTES>>>(src_features, edge_sh, edge_emb,
                                       W1, W2, src, dst, out);
}

// round 10
// speedup vs baseline: 1.1869x; 1.1099x over previous
#include <cuda_runtime.h>
#include <cstdint>

typedef unsigned long long u64;

#define E_CNT 100000
#define NDST  10000
#define OUTC  2048

// ---------------- small device scratch (CSR only) ----------------
__device__ int g_counts[NDST];
__device__ int g_cursor[NDST];
__device__ int g_eid   [E_CNT];

// ---------------- prologue kernels ----------------
__global__ void zero_cnt_k() {
    int i = blockIdx.x * blockDim.x + threadIdx.x;
    if (i < NDST) g_counts[i] = 0;
}
__global__ void hist_k(const int* __restrict__ dst) {
    int e = blockIdx.x * blockDim.x + threadIdx.x;
    if (e < E_CNT) atomicAdd(&g_counts[dst[e]], 1);
}
__global__ void scan_k() {
    __shared__ int ss[1024];
    const int tid = threadIdx.x;
    const int CH = 10;
    int base = tid * CH, loc[CH], s = 0;
#pragma unroll
    for (int i = 0; i < CH; i++) {
        int idx = base + i;
        int v = (idx < NDST) ? g_counts[idx] : 0;
        loc[i] = s; s += v;
    }
    ss[tid] = s; __syncthreads();
    for (int off = 1; off < 1024; off <<= 1) {
        int v = 0;
        if (tid >= off) v = ss[tid - off];
        __syncthreads();
        if (tid >= off) ss[tid] += v;
        __syncthreads();
    }
    int excl = (tid == 0) ? 0 : ss[tid - 1];
#pragma unroll
    for (int i = 0; i < CH; i++) {
        int idx = base + i;
        if (idx < NDST) g_cursor[idx] = excl + loc[i];
    }
}
__global__ void fill_k(const int* __restrict__ dst) {
    int e = blockIdx.x * blockDim.x + threadIdx.x;
    if (e < E_CNT) {
        int p = atomicAdd(&g_cursor[dst[e]], 1);
        g_eid[p] = e;
    }
}
__global__ void zero_out_k(float4* __restrict__ out, int n4) {
    int i = blockIdx.x * blockDim.x + threadIdx.x;
    if (i < n4) out[i] = make_float4(0.f, 0.f, 0.f, 0.f);
}

// ---------------- packed fp32x2 helpers ----------------
__device__ __forceinline__ void ffma2(u64& d, u64 a, u64 b) {
    asm("fma.rn.f32x2 %0, %1, %2, %0;" : "+l"(d) : "l"(a), "l"(b));
}
__device__ __forceinline__ u64 pack2(float x) {
    u64 r; asm("mov.b64 %0, {%1, %1};" : "=l"(r) : "f"(x)); return r;
}
__device__ __forceinline__ u64 packf2(float lo, float hi) {
    u64 r; asm("mov.b64 %0, {%1, %2};" : "=l"(r) : "f"(lo), "f"(hi)); return r;
}
__device__ __forceinline__ float2 unpack2(u64 v) {
    float2 f; asm("mov.b64 {%0, %1}, %2;" : "=f"(f.x), "=f"(f.y) : "l"(v)); return f;
}
__device__ __forceinline__ float silu_f(float x) {
    return x / (1.f + __expf(-x));
}

// ---------------- smem layout (float offsets) ----------------
// Hst [128][66] 33792B | Ws [64][128] 32768B (EMBt [64][66] aliases) |
// W1s [64][128] 32768B (TPW [64][128] aliases) | SHs [64][16] 4096B | ints
#define F_HST  0            // 8448 floats
#define F_WS   8448         // 8192 floats (EMBt aliases: 4224)
#define F_W1S  16640        // 8192 floats (TPW aliases)
#define F_SHS  24832        // 1024 floats
#define F_END  25856
#define SMEM_BYTES ((F_END + 192) * 4)

// ---------------- fused kernel: FFMA2 MLP + TP + segment scatter -----------
__global__ __launch_bounds__(256, 2) void fused_k(
    const float* __restrict__ src_features,
    const float* __restrict__ edge_sh,
    const float* __restrict__ edge_emb,
    const float* __restrict__ W1,
    const float* __restrict__ W2,
    const int*   __restrict__ src,
    const int*   __restrict__ dst,
    float*       __restrict__ out)
{
    extern __shared__ float sm[];
    float* Hst  = sm + F_HST;    // [k=128][row 64+2pad]
    float* Ws   = sm + F_WS;     // [k=64][n 128]
    float* EMBt = Ws;            // [k=64][row 64+2pad] alias
    float* W1s  = sm + F_W1S;    // [k=64][n 128]
    float* TPW  = W1s;           // [row 64][c 128] alias
    float* SHs  = sm + F_SHS;    // [row 64][16]
    int*   Es   = (int*)(sm + F_END);
    int*   Ss   = Es + 64;
    int*   Ds   = Ss + 64;

    const int tid = threadIdx.x;
    const int tr  = tid >> 5;     // warp id 0..7 -> rows tr*8 .. tr*8+7
    const int tc  = tid & 31;     // lane -> cols tc*4 .. tc*4+3
    const int r0  = tr * 8;
    const int c0  = tc * 4;

    // ---- stage edge metadata (pads replicate last edge; SH pads -> 0) ----
    const int pos0 = blockIdx.x * 64;
    const int nE   = (E_CNT - pos0 < 64) ? (E_CNT - pos0) : 64;
    if (tid < 64) {
        int sl = (tid < nE) ? tid : (nE - 1);
        int e  = g_eid[pos0 + sl];
        Es[tid] = e; Ss[tid] = src[e]; Ds[tid] = dst[e];
    }
    __syncthreads();

    // ---- stage EMBt (transposed), W1s (scaled), SHs ----
#pragma unroll
    for (int it = 0; it < 4; it++) {           // EMB: 64 x 16 float4 -> EMBt[k][row]
        int li = tid + it * 256;
        int slot = li >> 4, f = li & 15;
        float4 v = *(const float4*)&edge_emb[(size_t)Es[slot] * 64 + f * 4];
        EMBt[(f * 4 + 0) * 66 + slot] = v.x;
        EMBt[(f * 4 + 1) * 66 + slot] = v.y;
        EMBt[(f * 4 + 2) * 66 + slot] = v.z;
        EMBt[(f * 4 + 3) * 66 + slot] = v.w;
    }
#pragma unroll
    for (int it = 0; it < 8; it++) {           // W1s[k][n] = W1[k][n]/8
        int li = tid + it * 256;
        int k = li >> 5, f = li & 31;
        float4 v = *(const float4*)&W1[(size_t)k * 128 + f * 4];
        v.x *= 0.125f; v.y *= 0.125f; v.z *= 0.125f; v.w *= 0.125f;
        *(float4*)&W1s[k * 128 + f * 4] = v;
    }
    {                                          // SHs: 64 x 4 float4 (zero pads)
        int slot = tid >> 2, j = tid & 3;
        float4 v = make_float4(0.f, 0.f, 0.f, 0.f);
        if (slot < nE)
            v = *(const float4*)&edge_sh[(size_t)Es[slot] * 16 + j * 4];
        *(float4*)&SHs[slot * 16 + j * 4] = v;
    }
    __syncthreads();

    // ---- GEMM1: Hst = silu(EMB @ W1s)^T, 64x128x64, FFMA2 ----
    {
        u64 acc[4][4];   // [row-pair p][col j]: {row r0+2p, row r0+2p+1}
#pragma unroll
        for (int p = 0; p < 4; p++)
#pragma unroll
            for (int j = 0; j < 4; j++) acc[p][j] = 0ull;

#pragma unroll 8
        for (int kk = 0; kk < 64; kk++) {
            float4 rb = *(const float4*)&W1s[kk * 128 + c0];
            u64 bb0 = pack2(rb.x), bb1 = pack2(rb.y);
            u64 bb2 = pack2(rb.z), bb3 = pack2(rb.w);
#pragma unroll
            for (int p = 0; p < 4; p++) {
                u64 ap = *(const u64*)&EMBt[kk * 66 + r0 + 2 * p];  // broadcast pair
                ffma2(acc[p][0], ap, bb0); ffma2(acc[p][1], ap, bb1);
                ffma2(acc[p][2], ap, bb2); ffma2(acc[p][3], ap, bb3);
            }
        }
        // epilogue: silu -> Hst[c][row] (pair store)
#pragma unroll
        for (int p = 0; p < 4; p++)
#pragma unroll
            for (int j = 0; j < 4; j++) {
                float2 v = unpack2(acc[p][j]);
                v.x = silu_f(v.x); v.y = silu_f(v.y);
                *(u64*)&Hst[(c0 + j) * 66 + r0 + 2 * p] = packf2(v.x, v.y);
            }
    }
    __syncthreads();   // Hst ready; EMBt(Ws) and W1s(TPW) free

    // ---- per-l: GEMM2 (FFMA2) + fold x + run-length segment scatter ----
    const float w2s = 0.08838834764831845f;    // 1/sqrt(128)

    for (int l = 0; l < 4; l++) {
        u64 acc[4][4];
#pragma unroll
        for (int p = 0; p < 4; p++)
#pragma unroll
            for (int j = 0; j < 4; j++) acc[p][j] = 0ull;

        for (int k0 = 0; k0 < 128; k0 += 64) {
            if (k0) __syncthreads();           // Ws reuse guard within l
            // stage Ws[k][n] = W2[k0+k][l*128+n] * w2s
#pragma unroll
            for (int it = 0; it < 8; it++) {
                int li = tid + it * 256;
                int k = li >> 5, f = li & 31;
                float4 v = *(const float4*)&W2[(size_t)(k0 + k) * 512 + l * 128 + f * 4];
                v.x *= w2s; v.y *= w2s; v.z *= w2s; v.w *= w2s;
                *(float4*)&Ws[k * 128 + f * 4] = v;
            }
            __syncthreads();

#pragma unroll 8
            for (int kk = 0; kk < 64; kk++) {
                float4 rb = *(const float4*)&Ws[kk * 128 + c0];
                u64 bb0 = pack2(rb.x), bb1 = pack2(rb.y);
                u64 bb2 = pack2(rb.z), bb3 = pack2(rb.w);
#pragma unroll
                for (int p = 0; p < 4; p++) {
                    u64 ap = *(const u64*)&Hst[(k0 + kk) * 66 + r0 + 2 * p];
                    ffma2(acc[p][0], ap, bb0); ffma2(acc[p][1], ap, bb1);
                    ffma2(acc[p][2], ap, bb2); ffma2(acc[p][3], ap, bb3);
                }
            }
        }
        __syncthreads();   // Ws reads + previous TPW use complete

        // fold: TPW[row][c] = acc * x_src[src[row]][c]
#pragma unroll
        for (int p = 0; p < 4; p++) {
            int rA = r0 + 2 * p, rB = rA + 1;
            float4 xA = *(const float4*)&src_features[(size_t)Ss[rA] * 128 + c0];
            float4 xB = *(const float4*)&src_features[(size_t)Ss[rB] * 128 + c0];
            float2 q0 = unpack2(acc[p][0]), q1 = unpack2(acc[p][1]);
            float2 q2 = unpack2(acc[p][2]), q3 = unpack2(acc[p][3]);
            float4 vA = make_float4(q0.x * xA.x, q1.x * xA.y, q2.x * xA.z, q3.x * xA.w);
            float4 vB = make_float4(q0.y * xB.x, q1.y * xB.y, q2.y * xB.z, q3.y * xB.w);
            *(float4*)&TPW[rA * 128 + c0] = vA;
            *(float4*)&TPW[rB * 128 + c0] = vB;
        }
        __syncthreads();

        // scatter: run-length reduce over 64 dst-sorted edges
        {
            const int d    = 2 * l + 1;
            const int soff = l * l;
            const int ob   = (l == 0) ? 0 : (l == 1) ? 128 : (l == 2) ? 512 : 1152;
            const int ncol = 128 * d;
            for (int q = tid; q < ncol; q += 256) {
                const int c = q / d;
                const int s = q - c * d;
                float a = 0.f;
                int cur = Ds[0];
#pragma unroll 8
                for (int e = 0; e < 64; e++) {
                    int dn = Ds[e];
                    if (dn != cur) {
                        atomicAdd(&out[(size_t)cur * OUTC + ob + q], a);
                        a = 0.f; cur = dn;
                    }
                    a += TPW[e * 128 + c] * SHs[e * 16 + soff + s];
                }
                atomicAdd(&out[(size_t)cur * OUTC + ob + q], a);
            }
        }
        __syncthreads();
    }
}

// ---------------- launch ----------------
extern "C" void kernel_launch(void* const* d_in, const int* in_sizes, int n_in,
                              void* d_out, int out_size)
{
    const float* src_features = (const float*)d_in[0];
    const float* edge_sh      = (const float*)d_in[1];
    const float* edge_emb     = (const float*)d_in[2];
    const float* W1           = (const float*)d_in[3];
    const float* W2           = (const float*)d_in[4];
    const int*   src          = (const int*)d_in[5];
    const int*   dst          = (const int*)d_in[6];
    float*       out          = (float*)d_out;
    (void)in_sizes; (void)n_in; (void)out_size;

    static bool attr_done = false;
    if (!attr_done) {
        cudaFuncSetAttribute(fused_k, cudaFuncAttributeMaxDynamicSharedMemorySize,
                             SMEM_BYTES);
        attr_done = true;
    }

    // CSR build
    zero_cnt_k<<<(NDST + 255) / 256, 256>>>();
    hist_k<<<(E_CNT + 255) / 256, 256>>>(dst);
    scan_k<<<1, 1024>>>();
    fill_k<<<(E_CNT + 255) / 256, 256>>>(dst);

    // zero output (atomic accumulation target)
    const int n4 = NDST * OUTC / 4;
    zero_out_k<<<(n4 + 255) / 256, 256>>>((float4*)out, n4);

    // fused FFMA2 MLP + TP + scatter (64 edges/block, 2 CTAs/SM)
    const int nblk = (E_CNT + 63) / 64;
    fused_k<<<nblk, 256, SMEM_BYTES>>>(src_features, edge_sh, edge_emb,
                                       W1, W2, src, dst, out);
}